// round 1
// baseline (speedup 1.0000x reference)
#include <cuda_runtime.h>
#include <math.h>

// Problem constants
#define CDIM    64
#define NE      2048
#define HW      4096
#define BATCH   16
#define NPIX    65536            // BATCH * HW
#define NELEM   4194304          // NPIX * CDIM

// Output layout (tuple flattened): z_q [NELEM], loss [1], perplexity [1], indices [NPIX]
#define OFF_LOSS  NELEM
#define OFF_PERP  (NELEM + 1)
#define OFF_IDX   (NELEM + 2)

// Argmax kernel tiling
#define BP      128              // pixels per block
#define THREADS 256
#define CHUNK   64               // codes per smem chunk
#define NCHUNK  (NE / CHUNK)     // 32
#define EPAD    65               // padded row (floats) for codebook tile
#define SMEM_FLOATS (CDIM * BP + 2 * CHUNK * EPAD)
#define SMEM_BYTES  (SMEM_FLOATS * 4)

#define OUTBLOCKS 4096           // vq_out grid (NELEM / (256*4))

__device__ int   g_idx[NPIX];
__device__ int   g_counts[NE];
__device__ float g_partials[OUTBLOCKS];

// ---------------------------------------------------------------------------
// Kernel 0: zero the histogram (graph replays need fresh counts every launch)
// ---------------------------------------------------------------------------
__global__ void vq_zero() {
    int t = threadIdx.x;
#pragma unroll
    for (int i = 0; i < NE / THREADS; ++i)
        g_counts[i * THREADS + t] = 0;
}

// ---------------------------------------------------------------------------
// Kernel 1: fused GEMM-argmax.  Each block: 128 pixels x all 2048 codes.
// Thread tile: 8 pixels (4 f32x2 pairs) x 4 codes, fma.rn.f32x2 mainloop.
// ---------------------------------------------------------------------------
__global__ void __launch_bounds__(THREADS, 2)
vq_argmax(const float* __restrict__ z, const float* __restrict__ cb,
          float* __restrict__ out, int out_size) {
    extern __shared__ float smem[];
    float* zs  = smem;                      // [CDIM][BP]  (k-major z tile)
    float* es0 = smem + CDIM * BP;          // 2 x [CHUNK][EPAD] (code-major, padded)

    const int tid = threadIdx.x;
    const int tx  = tid & 15;               // code group (4 codes)
    const int ty  = tid >> 4;               // pixel group (8 pixels)

    const int pixBase = blockIdx.x * BP;
    const int b       = pixBase >> 12;      // image (BP=128 divides HW=4096)
    const int hwBase  = pixBase & 4095;
    const float* zimg = z + (size_t)b * CDIM * HW + hwBase;

    // ---- load z tile: zs[c][p], coalesced over p ----
#pragma unroll
    for (int it = 0; it < (CDIM * BP) / THREADS; ++it) {   // 32 iters
        int item = it * THREADS + tid;
        int c = item >> 7, p = item & 127;
        zs[c * BP + p] = zimg[c * HW + p];
    }

    // ---- prefetch chunk 0 of codebook into regs ----
    float4 pre[4];
    {
        const float4* cb4 = (const float4*)cb;   // row = 16 float4
#pragma unroll
        for (int it = 0; it < 4; ++it)
            pre[it] = cb4[it * THREADS + tid];   // item: n=item>>4, kq=item&15
    }
    __syncthreads();

    // ---- store chunk 0 into buffer 0 ----
#pragma unroll
    for (int it = 0; it < 4; ++it) {
        int item = it * THREADS + tid;
        int n = item >> 4, kq = item & 15;
        float* d = es0 + n * EPAD + kq * 4;
        d[0] = pre[it].x; d[1] = pre[it].y; d[2] = pre[it].z; d[3] = pre[it].w;
    }
    __syncthreads();

    float mx[8];
    int   mi[8];
#pragma unroll
    for (int i = 0; i < 8; ++i) { mx[i] = -3.402823e38f; mi[i] = 0; }

    const float* zrow = zs + ty * 8;

    for (int ch = 0; ch < NCHUNK; ++ch) {
        const float* es = es0 + (ch & 1) * (CHUNK * EPAD);

        // prefetch next chunk (global -> regs) while computing
        if (ch + 1 < NCHUNK) {
            const float4* cb4 = (const float4*)(cb + (size_t)(ch + 1) * CHUNK * CDIM);
#pragma unroll
            for (int it = 0; it < 4; ++it)
                pre[it] = cb4[it * THREADS + tid];
        }

        // accumulators: 4 codes x 4 pixel-pairs, packed f32x2
        unsigned long long acc[4][4];
#pragma unroll
        for (int n = 0; n < 4; ++n)
#pragma unroll
            for (int j = 0; j < 4; ++j) acc[n][j] = 0ull;

        const float* erow = es + (tx * 4) * EPAD;

#pragma unroll
        for (int k = 0; k < CHUNK; ++k) {
            // 8 pixels: two LDS.128, reinterpreted as 4 f32x2 pairs
            const ulonglong2 a0 = *(const ulonglong2*)(zrow + k * BP);
            const ulonglong2 a1 = *(const ulonglong2*)(zrow + k * BP + 4);
            unsigned long long za[4] = { a0.x, a0.y, a1.x, a1.y };
#pragma unroll
            for (int n = 0; n < 4; ++n) {
                float ev = erow[n * EPAD + k];
                unsigned long long ep;
                asm("mov.b64 %0, {%1, %1};" : "=l"(ep) : "f"(ev));
#pragma unroll
                for (int j = 0; j < 4; ++j)
                    asm("fma.rn.f32x2 %0, %1, %2, %0;"
                        : "+l"(acc[n][j]) : "l"(za[j]), "l"(ep));
            }
        }

        // fold chunk results into running argmax (ascending code order ->
        // strict > keeps lowest index on ties, matching jnp.argmax)
        const int codeBase = ch * CHUNK + tx * 4;
#pragma unroll
        for (int n = 0; n < 4; ++n) {
            const int code = codeBase + n;
#pragma unroll
            for (int j = 0; j < 4; ++j) {
                unsigned int lo, hi;
                asm("mov.b64 {%0, %1}, %2;" : "=r"(lo), "=r"(hi) : "l"(acc[n][j]));
                float v0 = __uint_as_float(lo), v1 = __uint_as_float(hi);
                if (v0 > mx[2 * j])     { mx[2 * j]     = v0; mi[2 * j]     = code; }
                if (v1 > mx[2 * j + 1]) { mx[2 * j + 1] = v1; mi[2 * j + 1] = code; }
            }
        }

        __syncthreads();
        if (ch + 1 < NCHUNK) {
            float* esn = es0 + ((ch + 1) & 1) * (CHUNK * EPAD);
#pragma unroll
            for (int it = 0; it < 4; ++it) {
                int item = it * THREADS + tid;
                int n = item >> 4, kq = item & 15;
                float* d = esn + n * EPAD + kq * 4;
                d[0] = pre[it].x; d[1] = pre[it].y; d[2] = pre[it].z; d[3] = pre[it].w;
            }
            __syncthreads();
        }
    }

    // ---- reduce argmax across the 16 code-group lanes (xor stays in 16-lane half) ----
#pragma unroll
    for (int off = 8; off; off >>= 1) {
#pragma unroll
        for (int i = 0; i < 8; ++i) {
            float om = __shfl_xor_sync(0xFFFFFFFFu, mx[i], off);
            int   oi = __shfl_xor_sync(0xFFFFFFFFu, mi[i], off);
            if (om > mx[i] || (om == mx[i] && oi < mi[i])) { mx[i] = om; mi[i] = oi; }
        }
    }

    if (tx == 0) {
        const int p0 = pixBase + ty * 8;
#pragma unroll
        for (int i = 0; i < 8; ++i) {
            int p = p0 + i;
            g_idx[p] = mi[i];
            atomicAdd(&g_counts[mi[i]], 1);
            int o = OFF_IDX + p;
            if (o < out_size) out[o] = (float)mi[i];
        }
    }
}

// ---------------------------------------------------------------------------
// Kernel 2: z_q gather + straight-through output + per-block MSE partials.
// One thread = 4 consecutive output elements (same c, consecutive hw).
// ---------------------------------------------------------------------------
__global__ void __launch_bounds__(256)
vq_out(const float* __restrict__ z, const float* __restrict__ cb,
       float* __restrict__ out) {
    const int t = blockIdx.x * 256 + threadIdx.x;   // float4 index
    const int e = t * 4;
    const int c  = (e >> 12) & 63;
    const int b  = e >> 18;
    const int hw = e & 4095;
    const int p  = (b << 12) + hw;

    const float4 zv = *(const float4*)(z + e);
    const int4  iv  = *(const int4*)(g_idx + p);

    const float q0 = cb[iv.x * CDIM + c];
    const float q1 = cb[iv.y * CDIM + c];
    const float q2 = cb[iv.z * CDIM + c];
    const float q3 = cb[iv.w * CDIM + c];

    // straight-through value: zp + (z_q - zp), computed as written (fp rounding match)
    float4 ov;
    ov.x = zv.x + (q0 - zv.x);
    ov.y = zv.y + (q1 - zv.y);
    ov.z = zv.z + (q2 - zv.z);
    ov.w = zv.w + (q3 - zv.w);
    *(float4*)(out + e) = ov;

    const float d0 = q0 - zv.x, d1 = q1 - zv.y, d2 = q2 - zv.z, d3 = q3 - zv.w;
    float s = d0 * d0 + d1 * d1 + d2 * d2 + d3 * d3;

    __shared__ float red[256];
    red[threadIdx.x] = s;
    __syncthreads();
#pragma unroll
    for (int off = 128; off; off >>= 1) {
        if (threadIdx.x < off) red[threadIdx.x] += red[threadIdx.x + off];
        __syncthreads();
    }
    if (threadIdx.x == 0) g_partials[blockIdx.x] = red[0];
}

// ---------------------------------------------------------------------------
// Kernel 3: deterministic finalize — loss and perplexity.
// ---------------------------------------------------------------------------
__global__ void vq_fin(float* __restrict__ out, int out_size) {
    __shared__ float red[256];
    const int t = threadIdx.x;

    float s = 0.0f;
    for (int i = t; i < OUTBLOCKS; i += 256) s += g_partials[i];
    red[t] = s;
    __syncthreads();
#pragma unroll
    for (int off = 128; off; off >>= 1) {
        if (t < off) red[t] += red[t + off];
        __syncthreads();
    }
    if (t == 0 && OFF_LOSS < out_size)
        out[OFF_LOSS] = 1.25f * red[0] * (1.0f / (float)NELEM);
    __syncthreads();

    float h = 0.0f;
    for (int i = t; i < NE; i += 256) {
        float em = (float)g_counts[i] * (1.0f / (float)NPIX);
        h += em * logf(em + 1e-10f);
    }
    red[t] = h;
    __syncthreads();
#pragma unroll
    for (int off = 128; off; off >>= 1) {
        if (t < off) red[t] += red[t + off];
        __syncthreads();
    }
    if (t == 0 && OFF_PERP < out_size)
        out[OFF_PERP] = expf(-red[0]);
}

// ---------------------------------------------------------------------------
extern "C" void kernel_launch(void* const* d_in, const int* in_sizes, int n_in,
                              void* d_out, int out_size) {
    const float* z  = (const float*)d_in[0];
    const float* cb = (const float*)d_in[1];
    float* out = (float*)d_out;

    cudaFuncSetAttribute(vq_argmax, cudaFuncAttributeMaxDynamicSharedMemorySize,
                         SMEM_BYTES);

    vq_zero<<<1, THREADS>>>();
    vq_argmax<<<NPIX / BP, THREADS, SMEM_BYTES>>>(z, cb, out, out_size);
    vq_out<<<OUTBLOCKS, 256>>>(z, cb, out);
    vq_fin<<<1, 256>>>(out, out_size);
}